// round 16
// baseline (speedup 1.0000x reference)
#include <cuda_runtime.h>
#include <cuda_fp16.h>
#include <math.h>
#include <stdint.h>

#define BB    2048
#define DD    256
#define HH    512
#define NSLOT 64
#define FEAT  513
#define MEMW  512           // mem_seq width in the GEMM (slots|cum); delta via epilogue
#define G4    2048
#define KSTEP 1024          // 512 (h) + 512 (mem)
#define KOUT  1280          // 256 (x) + 512 (h_mem) + 512 (h_lstm)

#define OFF_H      ((size_t)0)
#define OFF_C      ((size_t)1048576)
#define OFF_HMEM   ((size_t)2097152)
#define OFF_SLOTS  ((size_t)3145728)
#define OFF_CUM    ((size_t)36700160)
#define OFF_DELTA  ((size_t)70254592)
#define OFF_FILLED ((size_t)70385664)

// ------------------------------- scratch ------------------------------------
__device__ __half g_qh[BB * HH];
__device__ float  g_kq[BB * DD];
__device__ float  g_v[BB * DD];
__device__ int    g_idx[BB];
__device__ float  g_bias[G4];
__device__ float  g_biaso[G4];
__device__ float  g_wdt[G4];                     // permuted Wih[:,512] (delta col)
__device__ __half g_wstep[(size_t)G4 * KSTEP];   // [Whh | Wih[:, :512]] permuted
__device__ __half g_wout[(size_t)G4 * KOUT];
__device__ __half g_xh[BB * DD];
__device__ __half g_hlh[BB * HH];
__device__ __half g_wqh[HH * DD];
__device__ __half g_wkT[DD * HH];
__device__ __half g_wvh[DD * DD];
__device__ __half g_mem[(size_t)NSLOT * BB * MEMW];  // [n][b][slots|cum] fp16
__device__ float  g_dt[(size_t)NSLOT * BB];          // delta per (n,b), fp32
__device__ __half g_h0[BB * HH];
__device__ __half g_h1[BB * HH];
__device__ float  g_c[BB * HH];
__device__ int    g_barc[NSLOT * 16];     // per-(step, bm-group) barrier counters
__device__ int    g_fmode;

__device__ __forceinline__ float sigf(float x) { return 1.0f / (1.0f + __expf(-x)); }
__device__ __forceinline__ float tanh_fast(float x) {
    float t = __expf(-2.0f * fabsf(x));
    float r = (1.0f - t) / (1.0f + t);
    return copysignf(r, x);
}

__device__ __forceinline__ int read_filled(const void* p, size_t i, int m) {
    if (m == 0) return ((const float*)p)[i] != 0.0f;
    if (m == 1) return ((const int*)p)[i] != 0;
    if (m == 2) return ((const unsigned char*)p)[i] != 0;
    return ((const unsigned short*)p)[i] != 0;
}

// ----------------------------- PTX helpers ----------------------------------
__device__ __forceinline__ uint32_t smem_u32(const void* p) {
    uint32_t a;
    asm("{ .reg .u64 t; cvta.to.shared.u64 t, %1; cvt.u32.u64 %0, t; }" : "=r"(a) : "l"(p));
    return a;
}
__device__ __forceinline__ void cpasync16(uint32_t dst, const void* src) {
    asm volatile("cp.async.cg.shared.global [%0], [%1], 16;\n" :: "r"(dst), "l"(src));
}
#define CP_COMMIT() asm volatile("cp.async.commit_group;\n" ::: "memory")
#define CP_WAIT1()  asm volatile("cp.async.wait_group 1;\n" ::: "memory")

__device__ __forceinline__ void mma16(float* c, const uint32_t* A, const uint32_t* B) {
    asm volatile(
        "mma.sync.aligned.m16n8k16.row.col.f32.f16.f16.f32 "
        "{%0,%1,%2,%3}, {%4,%5,%6,%7}, {%8,%9}, {%0,%1,%2,%3};"
        : "+f"(c[0]), "+f"(c[1]), "+f"(c[2]), "+f"(c[3])
        : "r"(A[0]), "r"(A[1]), "r"(A[2]), "r"(A[3]), "r"(B[0]), "r"(B[1]));
}
__device__ __forceinline__ void ldsm4(uint32_t* r, uint32_t addr) {
    asm volatile("ldmatrix.sync.aligned.m8n8.x4.shared.b16 {%0,%1,%2,%3}, [%4];"
                 : "=r"(r[0]), "=r"(r[1]), "=r"(r[2]), "=r"(r[3]) : "r"(addr));
}

// ------------------------- fp16 warp-MMA GEMM core --------------------------
#define PADH 72                              // 64 data halfs + 8 pad (LDSM conflict-free)
#define TILE_HALFS (128 * PADH)              // 9216
#define BUF_HALFS  (2 * TILE_HALFS)          // 18432 halfs = 36864 B
#define SMEM_DYN   (3 * BUF_HALFS * 2)       // 110592 B

struct Seg {                                  // segmented A operand (<=3 pieces)
    const __half *p0, *p1, *p2;
    int l0, l1, l2, e0, e1;
};

__device__ __forceinline__ void load_stage64(uint32_t smb, const Seg& s,
                                             const __half* W, int ldw,
                                             int bm, int bn, int k0, int tid, int buf) {
    const uint32_t base = smb + (uint32_t)buf * BUF_HALFS * 2;
    const __half* Ap; int lda, ka;
    if (k0 < s.e0)      { Ap = s.p0; lda = s.l0; ka = k0; }
    else if (k0 < s.e1) { Ap = s.p1; lda = s.l1; ka = k0 - s.e0; }
    else                { Ap = s.p2; lda = s.l2; ka = k0 - s.e1; }
#pragma unroll
    for (int i = 0; i < 4; i++) {
        int idx = tid + i * 256;
        int r = idx >> 3, c = idx & 7;
        cpasync16(base + (uint32_t)(r * PADH + c * 8) * 2,
                  Ap + (size_t)(bm + r) * lda + ka + c * 8);
    }
#pragma unroll
    for (int i = 0; i < 4; i++) {
        int idx = tid + i * 256;
        int r = idx >> 3, c = idx & 7;
        cpasync16(base + (TILE_HALFS + (uint32_t)(r * PADH + c * 8)) * 2,
                  W + (size_t)(bn + r) * ldw + k0 + c * 8);
    }
}

// per-lane ldmatrix offsets (byte) within a stage
struct LdsmOff { uint32_t a0, a1, b[4]; };
__device__ __forceinline__ LdsmOff make_off(int tid) {
    const int wid = tid >> 5, lane = tid & 31;
    const int wm = wid & 3, wn = wid >> 2;
    LdsmOff o;
    o.a0 = ((uint32_t)((wm * 32 + (lane & 15)) * PADH + 8 * (lane >> 4))) * 2;
    o.a1 = o.a0 + (uint32_t)(16 * PADH) * 2;
    const int lbrow = (lane & 7) + ((lane >> 4) << 3);
    const int lbcol = ((lane >> 3) & 1) * 8;
#pragma unroll
    for (int p = 0; p < 4; p++)
        o.b[p] = (uint32_t)(TILE_HALFS + (wn * 64 + p * 16 + lbrow) * PADH + lbcol) * 2;
    return o;
}

__device__ __forceinline__ void compute_tile(uint32_t stage, const LdsmOff& o,
                                             float acc[2][8][4]) {
#pragma unroll
    for (int blk = 0; blk < 4; blk++) {
        const uint32_t kboff = (uint32_t)blk * 32;   // 16 halfs = 32 bytes
        uint32_t af[2][4];
        ldsm4(af[0], stage + o.a0 + kboff);
        ldsm4(af[1], stage + o.a1 + kboff);
        uint32_t bf[8][2];
#pragma unroll
        for (int p = 0; p < 4; p++) {
            uint32_t t4[4];
            ldsm4(t4, stage + o.b[p] + kboff);
            bf[2 * p][0] = t4[0]; bf[2 * p][1] = t4[1];
            bf[2 * p + 1][0] = t4[2]; bf[2 * p + 1][1] = t4[3];
        }
#pragma unroll
        for (int mt = 0; mt < 2; mt++)
#pragma unroll
            for (int nt = 0; nt < 8; nt++)
                mma16(acc[mt][nt], af[mt], bf[nt]);
    }
}

__device__ __forceinline__ void gemm_loop(uint32_t smb, const Seg& s,
                                          const __half* W, int ldw,
                                          int K, int bm, int bn, int tid,
                                          const LdsmOff& o, float acc[2][8][4]) {
#pragma unroll
    for (int mt = 0; mt < 2; mt++)
#pragma unroll
        for (int nt = 0; nt < 8; nt++)
#pragma unroll
            for (int e = 0; e < 4; e++) acc[mt][nt][e] = 0.0f;

    const int KT = K >> 6;
    load_stage64(smb, s, W, ldw, bm, bn, 0, tid, 0);
    CP_COMMIT();
    if (KT > 1) load_stage64(smb, s, W, ldw, bm, bn, 64, tid, 1);
    CP_COMMIT();

    for (int kt = 0; kt < KT; kt++) {
        CP_WAIT1();
        __syncthreads();
        if (kt + 2 < KT)
            load_stage64(smb, s, W, ldw, bm, bn, (kt + 2) * 64, tid, (kt + 2) % 3);
        CP_COMMIT();
        compute_tile(smb + (uint32_t)(kt % 3) * BUF_HALFS * 2, o, acc);
    }
    __syncthreads();   // guard smem reuse by epilogue
}

// fused LSTM pointwise epilogue (gate columns permuted 4j+t)
// dt/wdt: optional rank-1 delta term  gates[row, 4u+t] += dt[bm+row] * wdt[bn+4u+t]
__device__ __forceinline__ void lstm_epilogue(float acc[2][8][4], float* gsm,
                                              const float* bias, const float* c_in,
                                              float* c_out, float* h_full, __half* h_tf,
                                              const float* dt, const float* wdt,
                                              int bm, int bn, int tid) {
    const int wid = tid >> 5, lane = tid & 31;
    const int wm = wid & 3, wn = wid >> 2;
    const int gid = lane >> 2, tg = lane & 3;
#pragma unroll
    for (int mt = 0; mt < 2; mt++) {
        const int lr0 = wm * 32 + mt * 16 + gid;
        const int lr1 = lr0 + 8;
#pragma unroll
        for (int nt = 0; nt < 8; nt++) {
            const int lc = wn * 64 + nt * 8 + tg * 2;
            float2 v0 = make_float2(acc[mt][nt][0], acc[mt][nt][1]);
            float2 v1 = make_float2(acc[mt][nt][2], acc[mt][nt][3]);
            float2 b2 = *(const float2*)(bias + bn + lc);
            v0.x += b2.x; v0.y += b2.y; v1.x += b2.x; v1.y += b2.y;
            *(float2*)&gsm[lr0 * 132 + lc] = v0;
            *(float2*)&gsm[lr1 * 132 + lc] = v1;
        }
    }
    __syncthreads();
    const int jb = bn >> 2;
#pragma unroll
    for (int it = 0; it < 16; it++) {
        int idx = tid + it * 256;
        int row = idx >> 5, u = idx & 31;
        float4 gt = *(float4*)&gsm[row * 132 + 4 * u];
        if (dt) {
            float dtv = dt[bm + row];
            float4 w4 = *(const float4*)&wdt[bn + 4 * u];
            gt.x = fmaf(dtv, w4.x, gt.x);
            gt.y = fmaf(dtv, w4.y, gt.y);
            gt.z = fmaf(dtv, w4.z, gt.z);
            gt.w = fmaf(dtv, w4.w, gt.w);
        }
        float ii = sigf(gt.x), ff = sigf(gt.y);
        float gg = tanh_fast(gt.z), oo = sigf(gt.w);
        size_t e = (size_t)(bm + row) * HH + jb + u;
        float c_new = ff * c_in[e] + ii * gg;
        float h_new = oo * tanh_fast(c_new);
        c_out[e] = c_new;
        if (h_full) h_full[e] = h_new;
        if (h_tf)   h_tf[e] = __float2half_rn(h_new);
    }
}

// ---------------------- persistent slot-LSTM chain kernel -------------------
// Per step, 16 k-tiles: tiles 0..7 = mem (K 512..1024, no cross-step dep),
// tiles 8..15 = h (K 0..512).
// Barrier is PER-BM-GROUP: consumer (bm,bn) reads h rows [bm, bm+128) only,
// produced by the 16 CTAs sharing bm. Each group has its own counter (to 16);
// arrive after the epilogue, spin deferred to iteration 6 (before first h load).
struct ChainArgs {
    const __half *mem, *W;
    const float *bias, *dt, *wdt;
    __half *h0, *h1;
    float *c, *hmem_out;
};

__global__ void __launch_bounds__(256, 2) chain_kernel(const ChainArgs ca) {
    extern __shared__ __half smh[];
    const uint32_t smb = smem_u32(smh);
    const int tid = threadIdx.x;
    const int bmg = blockIdx.x >> 4;
    const int bm = bmg * 128;
    const int bn = (blockIdx.x & 15) * 128;
    const LdsmOff o = make_off(tid);
    float acc[2][8][4];
    const int KT = KSTEP >> 6;   // 16; tiles 0..7 = mem, 8..15 = h

    for (int n = 0; n < NSLOT; n++) {
        const __half* hbuf = (n & 1) ? ca.h1 : ca.h0;
        const __half* memn = ca.mem + (size_t)n * BB * MEMW;
#pragma unroll
        for (int mt = 0; mt < 2; mt++)
#pragma unroll
            for (int nt = 0; nt < 8; nt++)
#pragma unroll
                for (int e = 0; e < 4; e++) acc[mt][nt][e] = 0.0f;

        // tile i -> k0: i<8 mem (512+64i), else h (64*(i-8)); lda = 512 both
        auto ld = [&](int i, int buf) {
            int k0 = (i < 8) ? 512 + 64 * i : 64 * (i - 8);
            const __half* Ap = (k0 < 512) ? hbuf : memn;
            int ka = k0 & 511;
            const uint32_t base = smb + (uint32_t)buf * BUF_HALFS * 2;
#pragma unroll
            for (int j = 0; j < 4; j++) {
                int idx = tid + j * 256;
                int r = idx >> 3, c2 = idx & 7;
                cpasync16(base + (uint32_t)(r * PADH + c2 * 8) * 2,
                          Ap + (size_t)(bm + r) * 512 + ka + c2 * 8);
            }
#pragma unroll
            for (int j = 0; j < 4; j++) {
                int idx = tid + j * 256;
                int r = idx >> 3, c2 = idx & 7;
                cpasync16(base + (TILE_HALFS + (uint32_t)(r * PADH + c2 * 8)) * 2,
                          ca.W + (size_t)(bn + r) * KSTEP + k0 + c2 * 8);
            }
        };

        ld(0, 0); CP_COMMIT();
        ld(1, 1); CP_COMMIT();
        for (int i = 0; i < KT; i++) {
            CP_WAIT1();
            __syncthreads();
            if (i == 6 && n > 0) {            // before first h-tile load (i+2==8)
                if (tid == 0) {
                    volatile int* bp = &g_barc[(n - 1) * 16 + bmg];
                    while (*bp < 16) __nanosleep(64);
                }
                __syncthreads();
                __threadfence();
            }
            if (i + 2 < KT) ld(i + 2, (i + 2) % 3);
            CP_COMMIT();
            compute_tile(smb + (uint32_t)(i % 3) * BUF_HALFS * 2, o, acc);
        }
        __syncthreads();   // guard smem reuse by epilogue

        lstm_epilogue(acc, (float*)smh, ca.bias, ca.c, ca.c,
                      (n == NSLOT - 1) ? ca.hmem_out : nullptr,
                      (n & 1) ? ca.h0 : ca.h1,
                      ca.dt + (size_t)n * BB, ca.wdt, bm, bn, tid);

        // release h writes + guard gsm against next step's loads, then arrive
        __threadfence();
        __syncthreads();
        if (tid == 0) atomicAdd(&g_barc[n * 16 + bmg], 1);
    }
}

// ------------------------- standalone GEMM kernel ----------------------------
struct GArgs {
    int lstm, K, ldw, ldc;
    Seg s;
    const __half *W;
    const float *bias, *c_in;
    float *C, *c_out, *h_full;
    __half *Ch;
};

__global__ void __launch_bounds__(256, 2) mma_gemm_kernel(const GArgs a) {
    extern __shared__ __half smh[];
    const uint32_t smb = smem_u32(smh);
    const int tid = threadIdx.x;
    const int wid = tid >> 5, lane = tid & 31;
    const int wm = wid & 3, wn = wid >> 2;
    const int gid = lane >> 2, tg = lane & 3;
    const int bm = blockIdx.y * 128;
    const int bn = blockIdx.x * 128;
    const LdsmOff o = make_off(tid);
    float acc[2][8][4];

    gemm_loop(smb, a.s, a.W, a.ldw, a.K, bm, bn, tid, o, acc);

    if (a.lstm) {
        lstm_epilogue(acc, (float*)smh, a.bias, a.c_in, a.c_out, a.h_full,
                      nullptr, nullptr, nullptr, bm, bn, tid);
        return;
    }
#pragma unroll
    for (int mt = 0; mt < 2; mt++) {
        const size_t r0 = (size_t)bm + wm * 32 + mt * 16 + gid;
        const size_t r1 = r0 + 8;
#pragma unroll
        for (int nt = 0; nt < 8; nt++) {
            const int col = bn + wn * 64 + nt * 8 + tg * 2;
            float2 v0 = make_float2(acc[mt][nt][0], acc[mt][nt][1]);
            float2 v1 = make_float2(acc[mt][nt][2], acc[mt][nt][3]);
            if (a.bias) {
                float2 b2 = *(const float2*)(a.bias + col);
                v0.x += b2.x; v0.y += b2.y; v1.x += b2.x; v1.y += b2.y;
            }
            if (a.Ch) {
                *(__half2*)(a.Ch + r0 * a.ldc + col) = __floats2half2_rn(v0.x, v0.y);
                *(__half2*)(a.Ch + r1 * a.ldc + col) = __floats2half2_rn(v1.x, v1.y);
            } else {
                *(float2*)(a.C + r0 * a.ldc + col) = v0;
                *(float2*)(a.C + r1 * a.ldc + col) = v1;
            }
        }
    }
}

static void launch_g(const GArgs& a, int M, int N) {
    dim3 grid(N / 128, M / 128);
    mma_gemm_kernel<<<grid, 256, SMEM_DYN>>>(a);
}

// ------------------------------ prep kernels --------------------------------
__device__ __forceinline__ int porig(int p) { return ((p & 3) << 9) | (p >> 2); }

#define Q0 ((size_t)G4 * KSTEP)
#define Q1 (Q0 + (size_t)G4 * KOUT)
#define Q2 (Q1 + (size_t)BB * DD)
#define Q3 (Q2 + (size_t)BB * HH)
#define Q4 (Q3 + (size_t)HH * DD)
#define Q5 (Q4 + (size_t)DD * HH)
#define Q6 (Q5 + (size_t)DD * DD)
#define Q7 (Q6 + G4)
#define Q8 (Q7 + G4)
#define Q9 (Q8 + G4)

__global__ void prep_kernel(const float* __restrict__ Wih, const float* __restrict__ Whh,
                            const float* __restrict__ bih, const float* __restrict__ bhh,
                            const float* __restrict__ Wiho, const float* __restrict__ Whho,
                            const float* __restrict__ biho,
                            const float* __restrict__ x, const float* __restrict__ hl,
                            const float* __restrict__ Wq, const float* __restrict__ Wk,
                            const float* __restrict__ Wv) {
    size_t e = (size_t)blockIdx.x * blockDim.x + threadIdx.x;
    if (e < Q0) {
        int p = (int)(e / KSTEP), k = (int)(e % KSTEP);
        float v;
        if (k < 512) v = Whh[(size_t)porig(p) * 512 + k];
        else         v = Wih[(size_t)porig(p) * FEAT + (k - 512)];
        g_wstep[e] = __float2half_rn(v);
    } else if (e < Q1) {
        size_t i = e - Q0; int p = (int)(i / KOUT), k = (int)(i % KOUT);
        float v = (k < 768) ? Wiho[(size_t)porig(p) * 768 + k]
                            : Whho[(size_t)porig(p) * 512 + (k - 768)];
        g_wout[i] = __float2half_rn(v);
    } else if (e < Q2) {
        size_t i = e - Q1; g_xh[i] = __float2half_rn(x[i]);
    } else if (e < Q3) {
        size_t i = e - Q2; g_hlh[i] = __float2half_rn(hl[i]);
    } else if (e < Q4) {
        size_t i = e - Q3; g_wqh[i] = __float2half_rn(Wq[i]);
    } else if (e < Q5) {
        size_t i = e - Q4; size_t d = i >> 9, h = i & 511;
        g_wkT[i] = __float2half_rn(Wk[h * 256 + d]);
    } else if (e < Q6) {
        size_t i = e - Q5; g_wvh[i] = __float2half_rn(Wv[i]);
    } else if (e < Q7) {
        int p = (int)(e - Q6); int o = porig(p);
        g_bias[p] = bih[o] + bhh[o];
    } else if (e < Q8) {
        int p = (int)(e - Q7);
        g_biaso[p] = biho[porig(p)];
    } else if (e < Q9) {
        int p = (int)(e - Q8);
        g_wdt[p] = Wih[(size_t)porig(p) * FEAT + 512];   // delta column, fp32
    }
}

__global__ void zero_hc_kernel() {
    int e = blockIdx.x * blockDim.x + threadIdx.x;
    if (e < BB * HH) { g_h0[e] = __float2half_rn(0.0f); g_c[e] = 0.0f; }
    if (e < NSLOT * 16) g_barc[e] = 0;
}

__global__ void detect_filled_kernel(const unsigned int* __restrict__ w) {
    __shared__ int flags[3];
    if (threadIdx.x < 3) flags[threadIdx.x] = 0;
    __syncthreads();
    for (int i = threadIdx.x; i < (BB * NSLOT) / 4; i += blockDim.x) {
        unsigned v = w[i];
        if (v == 0x3F800000u)      atomicOr(&flags[0], 1);
        else if (v == 0x3F803F80u) atomicOr(&flags[1], 1);
        else if (v > 1u)           atomicOr(&flags[2], 1);
    }
    __syncthreads();
    if (threadIdx.x == 0) {
        int m;
        if (flags[1])      m = 3;
        else if (flags[0]) m = 0;
        else if (flags[2]) m = 2;
        else               m = 1;
        g_fmode = m;
    }
}

__global__ void select_idx_kernel(const float* __restrict__ slots,
                                  const void* __restrict__ filled) {
    const int b = blockIdx.x;
    const int t = threadIdx.x;
    __shared__ float kq_s[DD];
    __shared__ float sims[NSLOT];
    __shared__ int   emp[NSLOT];
    for (int d = t; d < DD; d += NSLOT) kq_s[d] = g_kq[b * DD + d];
    __syncthreads();
    const float* sp = slots + ((size_t)b * NSLOT + t) * DD;
    float s = 0.0f;
    for (int d = 0; d < DD; d++) s = fmaf(sp[d], kq_s[d], s);
    sims[t] = s;
    emp[t]  = !read_filled(filled, (size_t)b * NSLOT + t, g_fmode);
    __syncthreads();
    if (t == 0) {
        int idx = -1;
        for (int n = 0; n < NSLOT; n++) if (emp[n]) { idx = n; break; }
        if (idx < 0) {
            float best = sims[0]; idx = 0;
            for (int n = 1; n < NSLOT; n++) if (sims[n] > best) { best = sims[n]; idx = n; }
        }
        g_idx[b] = idx;
    }
}

__global__ void update_write_kernel(const float* __restrict__ slots,
                                    const float* __restrict__ cum,
                                    const float* __restrict__ delta,
                                    const void* __restrict__ filled,
                                    const float* __restrict__ x,
                                    float* __restrict__ out) {
    size_t e = (size_t)blockIdx.x * blockDim.x + threadIdx.x;
    if (e >= (size_t)BB * NSLOT * DD) return;
    int d = (int)(e % DD);
    size_t bn = e / DD;
    int n = (int)(bn % NSLOT);
    int b = (int)(bn / NSLOT);
    int idx = g_idx[b];

    float xv = x[b * DD + d];
    float sl = slots[e];
    float cf = cum[e] + xv;
    if (n == idx) { sl = g_v[b * DD + d]; cf = xv; }

    out[OFF_SLOTS + e] = sl;
    out[OFF_CUM + e]   = cf;

    size_t mbase = ((size_t)n * BB + b) * MEMW;
    g_mem[mbase + d]      = __float2half_rn(sl);
    g_mem[mbase + DD + d] = __float2half_rn(cf);
    if (d == 0) {
        float dt = (n == idx) ? 0.0f : delta[bn] + 1.0f;
        out[OFF_DELTA + bn] = dt;
        g_dt[(size_t)n * BB + b] = dt;
        int fl = (n == idx) ? 1 : read_filled(filled, bn, g_fmode);
        out[OFF_FILLED + bn] = fl ? 1.0f : 0.0f;
    }
}

// --------------------------------- launch -----------------------------------
extern "C" void kernel_launch(void* const* d_in, const int* in_sizes, int n_in,
                              void* d_out, int out_size) {
    const float* x_t      = (const float*)d_in[0];
    const float* h_lstm   = (const float*)d_in[1];
    const float* c_lstm   = (const float*)d_in[2];
    const float* slots    = (const float*)d_in[4];
    const float* cum      = (const float*)d_in[5];
    const float* delta    = (const float*)d_in[6];
    const void*  filled   = (const void*)d_in[7];
    const float* Wq       = (const float*)d_in[8];
    const float* Wk       = (const float*)d_in[9];
    const float* Wv       = (const float*)d_in[10];
    const float* bv       = (const float*)d_in[11];
    const float* lstm_Wih = (const float*)d_in[12];
    const float* lstm_Whh = (const float*)d_in[13];
    const float* lstm_bih = (const float*)d_in[14];
    const float* lstm_bhh = (const float*)d_in[15];
    const float* W_ih     = (const float*)d_in[16];
    const float* b_ih     = (const float*)d_in[17];
    const float* W_hh     = (const float*)d_in[18];
    float* out = (float*)d_out;

    float *p_kq, *p_v, *p_c, *p_bias, *p_biaso, *p_dt, *p_wdt;
    __half *p_qh, *p_mem, *p_wstep, *p_wout, *p_xh, *p_hlh, *p_wqh, *p_wkT, *p_wvh;
    __half *p_h0, *p_h1;
    cudaGetSymbolAddress((void**)&p_qh, g_qh);
    cudaGetSymbolAddress((void**)&p_kq, g_kq);
    cudaGetSymbolAddress((void**)&p_v, g_v);
    cudaGetSymbolAddress((void**)&p_mem, g_mem);
    cudaGetSymbolAddress((void**)&p_c, g_c);
    cudaGetSymbolAddress((void**)&p_bias, g_bias);
    cudaGetSymbolAddress((void**)&p_biaso, g_biaso);
    cudaGetSymbolAddress((void**)&p_dt, g_dt);
    cudaGetSymbolAddress((void**)&p_wdt, g_wdt);
    cudaGetSymbolAddress((void**)&p_wstep, g_wstep);
    cudaGetSymbolAddress((void**)&p_wout, g_wout);
    cudaGetSymbolAddress((void**)&p_xh, g_xh);
    cudaGetSymbolAddress((void**)&p_hlh, g_hlh);
    cudaGetSymbolAddress((void**)&p_wqh, g_wqh);
    cudaGetSymbolAddress((void**)&p_wkT, g_wkT);
    cudaGetSymbolAddress((void**)&p_wvh, g_wvh);
    cudaGetSymbolAddress((void**)&p_h0, g_h0);
    cudaGetSymbolAddress((void**)&p_h1, g_h1);

    static int attr_set = 0;
    if (!attr_set) {
        cudaFuncSetAttribute(mma_gemm_kernel,
                             cudaFuncAttributeMaxDynamicSharedMemorySize, SMEM_DYN);
        cudaFuncSetAttribute(chain_kernel,
                             cudaFuncAttributeMaxDynamicSharedMemorySize, SMEM_DYN);
        attr_set = 1;
    }

    detect_filled_kernel<<<1, 256>>>((const unsigned int*)filled);
    zero_hc_kernel<<<(BB * HH + 255) / 256, 256>>>();
    prep_kernel<<<(unsigned)((Q9 + 255) / 256), 256>>>(
        lstm_Wih, lstm_Whh, lstm_bih, lstm_bhh,
        W_ih, W_hh, b_ih, x_t, h_lstm, Wq, Wk, Wv);

    GArgs a;
    // q = x @ Wq.T (fp16 store)
    a = {}; a.K = 256; a.ldw = 256; a.ldc = 512;
    a.s = { p_xh, nullptr, nullptr, 256, 0, 0, 256, 256 };
    a.W = p_wqh; a.Ch = p_qh;
    launch_g(a, BB, HH);
    // kq = q @ Wk
    a = {}; a.K = 512; a.ldw = 512; a.ldc = 256;
    a.s = { p_qh, nullptr, nullptr, 512, 0, 0, 512, 512 };
    a.W = p_wkT; a.C = p_kq;
    launch_g(a, BB, DD);
    // v = x @ Wv.T + bv
    a = {}; a.K = 256; a.ldw = 256; a.ldc = 256;
    a.s = { p_xh, nullptr, nullptr, 256, 0, 0, 256, 256 };
    a.W = p_wvh; a.bias = bv; a.C = p_v;
    launch_g(a, BB, DD);

    select_idx_kernel<<<BB, NSLOT>>>(slots, filled);
    {
        size_t tot = (size_t)BB * NSLOT * DD;
        update_write_kernel<<<(unsigned)((tot + 255) / 256), 256>>>(
            slots, cum, delta, filled, x_t, out);
    }

    // persistent slot-LSTM chain: per-bm-group barriers
    {
        ChainArgs ca;
        ca.mem = p_mem; ca.W = p_wstep; ca.bias = p_bias;
        ca.dt = p_dt; ca.wdt = p_wdt;
        ca.h0 = p_h0; ca.h1 = p_h1; ca.c = p_c;
        ca.hmem_out = out + OFF_HMEM;
        chain_kernel<<<256, 256, SMEM_DYN>>>(ca);
    }

    // outer LSTM: K = [x(256) | h_mem(512) | h_lstm(512)]
    a = {}; a.lstm = 1; a.K = KOUT; a.ldw = KOUT; a.ldc = G4;
    a.s = { p_xh, p_h0, p_hlh, 256, 512, 512, 256, 768 };   // n=63 odd -> h in p_h0
    a.W = p_wout; a.bias = p_biaso;
    a.c_in = c_lstm; a.c_out = out + OFF_C; a.h_full = out + OFF_H;
    launch_g(a, BB, G4);
}

// round 17
// speedup vs baseline: 1.1157x; 1.1157x over previous
#include <cuda_runtime.h>
#include <cuda_fp16.h>
#include <math.h>
#include <stdint.h>

#define BB    2048
#define DD    256
#define HH    512
#define NSLOT 64
#define FEAT  513
#define MEMW  512
#define G4    2048
#define KSTEP 1024          // 512 (h) + 512 (mem)
#define KOUT  1280          // 256 (x) + 512 (h_mem) + 512 (h_lstm)

#define OFF_H      ((size_t)0)
#define OFF_C      ((size_t)1048576)
#define OFF_HMEM   ((size_t)2097152)
#define OFF_SLOTS  ((size_t)3145728)
#define OFF_CUM    ((size_t)36700160)
#define OFF_DELTA  ((size_t)70254592)
#define OFF_FILLED ((size_t)70385664)

// ------------------------------- scratch ------------------------------------
__device__ float  g_v[BB * DD];
__device__ int    g_idx[BB];
__device__ float  g_bias[G4];
__device__ float  g_biaso[G4];
__device__ float  g_wdt[G4];                     // permuted Wih[:,512]
__device__ __half g_wstep[(size_t)G4 * KSTEP];   // [Whh | Wih[:, :512]] permuted
__device__ __half g_wout[(size_t)G4 * KOUT];
__device__ __half g_xh[BB * DD];
__device__ __half g_hlh[BB * HH];
__device__ __half g_wvh[DD * DD];
__device__ __half g_mem[(size_t)NSLOT * BB * MEMW];
__device__ float  g_dt[(size_t)NSLOT * BB];
__device__ __half g_h0[BB * HH];
__device__ __half g_h1[BB * HH];
__device__ float  g_c[BB * HH];
__device__ int    g_barc[NSLOT * 16];
__device__ int    g_fmode;

__device__ __forceinline__ float sigf(float x) { return 1.0f / (1.0f + __expf(-x)); }
__device__ __forceinline__ float tanh_fast(float x) {
    float t = __expf(-2.0f * fabsf(x));
    float r = (1.0f - t) / (1.0f + t);
    return copysignf(r, x);
}

__device__ __forceinline__ int read_filled(const void* p, size_t i, int m) {
    if (m == 0) return ((const float*)p)[i] != 0.0f;
    if (m == 1) return ((const int*)p)[i] != 0;
    if (m == 2) return ((const unsigned char*)p)[i] != 0;
    return ((const unsigned short*)p)[i] != 0;
}

// ----------------------------- PTX helpers ----------------------------------
__device__ __forceinline__ uint32_t smem_u32(const void* p) {
    uint32_t a;
    asm("{ .reg .u64 t; cvta.to.shared.u64 t, %1; cvt.u32.u64 %0, t; }" : "=r"(a) : "l"(p));
    return a;
}
__device__ __forceinline__ void cpasync16(uint32_t dst, const void* src) {
    asm volatile("cp.async.cg.shared.global [%0], [%1], 16;\n" :: "r"(dst), "l"(src));
}
#define CP_COMMIT() asm volatile("cp.async.commit_group;\n" ::: "memory")
#define CP_WAIT1()  asm volatile("cp.async.wait_group 1;\n" ::: "memory")
#define CP_WAIT0()  asm volatile("cp.async.wait_group 0;\n" ::: "memory")

__device__ __forceinline__ int ld_acquire(const int* p) {
    int v;
    asm volatile("ld.acquire.gpu.global.b32 %0, [%1];" : "=r"(v) : "l"(p) : "memory");
    return v;
}

__device__ __forceinline__ void mma16(float* c, const uint32_t* A, const uint32_t* B) {
    asm volatile(
        "mma.sync.aligned.m16n8k16.row.col.f32.f16.f16.f32 "
        "{%0,%1,%2,%3}, {%4,%5,%6,%7}, {%8,%9}, {%0,%1,%2,%3};"
        : "+f"(c[0]), "+f"(c[1]), "+f"(c[2]), "+f"(c[3])
        : "r"(A[0]), "r"(A[1]), "r"(A[2]), "r"(A[3]), "r"(B[0]), "r"(B[1]));
}
__device__ __forceinline__ void ldsm4(uint32_t* r, uint32_t addr) {
    asm volatile("ldmatrix.sync.aligned.m8n8.x4.shared.b16 {%0,%1,%2,%3}, [%4];"
                 : "=r"(r[0]), "=r"(r[1]), "=r"(r[2]), "=r"(r[3]) : "r"(addr));
}

// ------------------------- fp16 warp-MMA GEMM core --------------------------
#define PADH 72
#define TILE_HALFS (128 * PADH)
#define BUF_HALFS  (2 * TILE_HALFS)
#define SMEM_DYN   (3 * BUF_HALFS * 2)

struct Seg {
    const __half *p0, *p1, *p2;
    int l0, l1, l2, e0, e1;
};

__device__ __forceinline__ void load_stage64(uint32_t smb, const Seg& s,
                                             const __half* W, int ldw,
                                             int bm, int bn, int k0, int tid, int buf) {
    const uint32_t base = smb + (uint32_t)buf * BUF_HALFS * 2;
    const __half* Ap; int lda, ka;
    if (k0 < s.e0)      { Ap = s.p0; lda = s.l0; ka = k0; }
    else if (k0 < s.e1) { Ap = s.p1; lda = s.l1; ka = k0 - s.e0; }
    else                { Ap = s.p2; lda = s.l2; ka = k0 - s.e1; }
#pragma unroll
    for (int i = 0; i < 4; i++) {
        int idx = tid + i * 256;
        int r = idx >> 3, c = idx & 7;
        cpasync16(base + (uint32_t)(r * PADH + c * 8) * 2,
                  Ap + (size_t)(bm + r) * lda + ka + c * 8);
    }
#pragma unroll
    for (int i = 0; i < 4; i++) {
        int idx = tid + i * 256;
        int r = idx >> 3, c = idx & 7;
        cpasync16(base + (TILE_HALFS + (uint32_t)(r * PADH + c * 8)) * 2,
                  W + (size_t)(bn + r) * ldw + k0 + c * 8);
    }
}

struct LdsmOff { uint32_t a0, a1, b[4]; };
__device__ __forceinline__ LdsmOff make_off(int tid) {
    const int wid = tid >> 5, lane = tid & 31;
    const int wm = wid & 3, wn = wid >> 2;
    LdsmOff o;
    o.a0 = ((uint32_t)((wm * 32 + (lane & 15)) * PADH + 8 * (lane >> 4))) * 2;
    o.a1 = o.a0 + (uint32_t)(16 * PADH) * 2;
    const int lbrow = (lane & 7) + ((lane >> 4) << 3);
    const int lbcol = ((lane >> 3) & 1) * 8;
#pragma unroll
    for (int p = 0; p < 4; p++)
        o.b[p] = (uint32_t)(TILE_HALFS + (wn * 64 + p * 16 + lbrow) * PADH + lbcol) * 2;
    return o;
}

__device__ __forceinline__ void compute_tile(uint32_t stage, const LdsmOff& o,
                                             float acc[2][8][4]) {
#pragma unroll
    for (int blk = 0; blk < 4; blk++) {
        const uint32_t kboff = (uint32_t)blk * 32;
        uint32_t af[2][4];
        ldsm4(af[0], stage + o.a0 + kboff);
        ldsm4(af[1], stage + o.a1 + kboff);
        uint32_t bf[8][2];
#pragma unroll
        for (int p = 0; p < 4; p++) {
            uint32_t t4[4];
            ldsm4(t4, stage + o.b[p] + kboff);
            bf[2 * p][0] = t4[0]; bf[2 * p][1] = t4[1];
            bf[2 * p + 1][0] = t4[2]; bf[2 * p + 1][1] = t4[3];
        }
#pragma unroll
        for (int mt = 0; mt < 2; mt++)
#pragma unroll
            for (int nt = 0; nt < 8; nt++)
                mma16(acc[mt][nt], af[mt], bf[nt]);
    }
}

__device__ __forceinline__ void gemm_loop(uint32_t smb, const Seg& s,
                                          const __half* W, int ldw,
                                          int K, int bm, int bn, int tid,
                                          const LdsmOff& o, float acc[2][8][4]) {
#pragma unroll
    for (int mt = 0; mt < 2; mt++)
#pragma unroll
        for (int nt = 0; nt < 8; nt++)
#pragma unroll
            for (int e = 0; e < 4; e++) acc[mt][nt][e] = 0.0f;

    const int KT = K >> 6;
    load_stage64(smb, s, W, ldw, bm, bn, 0, tid, 0);
    CP_COMMIT();
    if (KT > 1) load_stage64(smb, s, W, ldw, bm, bn, 64, tid, 1);
    CP_COMMIT();

    for (int kt = 0; kt < KT; kt++) {
        CP_WAIT1();
        __syncthreads();
        if (kt + 2 < KT)
            load_stage64(smb, s, W, ldw, bm, bn, (kt + 2) * 64, tid, (kt + 2) % 3);
        CP_COMMIT();
        compute_tile(smb + (uint32_t)(kt % 3) * BUF_HALFS * 2, o, acc);
    }
    __syncthreads();
}

// fused LSTM pointwise epilogue (gate columns permuted 4j+t)
__device__ __forceinline__ void lstm_epilogue(float acc[2][8][4], float* gsm,
                                              const float* bias, const float* c_in,
                                              float* c_out, float* h_full, __half* h_tf,
                                              const float* dt, const float* wdt,
                                              int bm, int bn, int tid) {
    const int wid = tid >> 5, lane = tid & 31;
    const int wm = wid & 3, wn = wid >> 2;
    const int gid = lane >> 2, tg = lane & 3;
#pragma unroll
    for (int mt = 0; mt < 2; mt++) {
        const int lr0 = wm * 32 + mt * 16 + gid;
        const int lr1 = lr0 + 8;
#pragma unroll
        for (int nt = 0; nt < 8; nt++) {
            const int lc = wn * 64 + nt * 8 + tg * 2;
            float2 v0 = make_float2(acc[mt][nt][0], acc[mt][nt][1]);
            float2 v1 = make_float2(acc[mt][nt][2], acc[mt][nt][3]);
            float2 b2 = *(const float2*)(bias + bn + lc);
            v0.x += b2.x; v0.y += b2.y; v1.x += b2.x; v1.y += b2.y;
            *(float2*)&gsm[lr0 * 132 + lc] = v0;
            *(float2*)&gsm[lr1 * 132 + lc] = v1;
        }
    }
    __syncthreads();
    const int jb = bn >> 2;
#pragma unroll
    for (int it = 0; it < 16; it++) {
        int idx = tid + it * 256;
        int row = idx >> 5, u = idx & 31;
        float4 gt = *(float4*)&gsm[row * 132 + 4 * u];
        if (dt) {
            float dtv = dt[bm + row];
            float4 w4 = *(const float4*)&wdt[bn + 4 * u];
            gt.x = fmaf(dtv, w4.x, gt.x);
            gt.y = fmaf(dtv, w4.y, gt.y);
            gt.z = fmaf(dtv, w4.z, gt.z);
            gt.w = fmaf(dtv, w4.w, gt.w);
        }
        float ii = sigf(gt.x), ff = sigf(gt.y);
        float gg = tanh_fast(gt.z), oo = sigf(gt.w);
        size_t e = (size_t)(bm + row) * HH + jb + u;
        float c_new = ff * c_in[e] + ii * gg;
        float h_new = oo * tanh_fast(c_new);
        c_out[e] = c_new;
        if (h_full) h_full[e] = h_new;
        if (h_tf)   h_tf[e] = __float2half_rn(h_new);
    }
}

// ---------------------- persistent slot-LSTM chain kernel -------------------
// 16 k-tiles: 0..7 = mem (K 512..1024, independent), 8..15 = h (K 0..512).
// Tile 8 uses prefetch distance 1: no load at i==6; at i==7 drain, spin
// (acquire) on the per-bm-group counter, then issue tiles 8+9 and compute 7.
struct ChainArgs {
    const __half *mem, *W;
    const float *bias, *dt, *wdt;
    __half *h0, *h1;
    float *c, *hmem_out;
};

__global__ void __launch_bounds__(256, 2) chain_kernel(const ChainArgs ca) {
    extern __shared__ __half smh[];
    const uint32_t smb = smem_u32(smh);
    const int tid = threadIdx.x;
    const int bmg = blockIdx.x >> 4;
    const int bm = bmg * 128;
    const int bn = (blockIdx.x & 15) * 128;
    const LdsmOff o = make_off(tid);
    float acc[2][8][4];

    for (int n = 0; n < NSLOT; n++) {
        const __half* hbuf = (n & 1) ? ca.h1 : ca.h0;
        const __half* memn = ca.mem + (size_t)n * BB * MEMW;
#pragma unroll
        for (int mt = 0; mt < 2; mt++)
#pragma unroll
            for (int nt = 0; nt < 8; nt++)
#pragma unroll
                for (int e = 0; e < 4; e++) acc[mt][nt][e] = 0.0f;

        // tile i -> k0: i<8 mem (512+64i), else h (64*(i-8)); lda = 512 both
        auto ld = [&](int i, int buf) {
            int k0 = (i < 8) ? 512 + 64 * i : 64 * (i - 8);
            const __half* Ap = (k0 < 512) ? hbuf : memn;
            int ka = k0 & 511;
            const uint32_t base = smb + (uint32_t)buf * BUF_HALFS * 2;
#pragma unroll
            for (int j = 0; j < 4; j++) {
                int idx = tid + j * 256;
                int r = idx >> 3, c2 = idx & 7;
                cpasync16(base + (uint32_t)(r * PADH + c2 * 8) * 2,
                          Ap + (size_t)(bm + r) * 512 + ka + c2 * 8);
            }
#pragma unroll
            for (int j = 0; j < 4; j++) {
                int idx = tid + j * 256;
                int r = idx >> 3, c2 = idx & 7;
                cpasync16(base + (TILE_HALFS + (uint32_t)(r * PADH + c2 * 8)) * 2,
                          ca.W + (size_t)(bn + r) * KSTEP + k0 + c2 * 8);
            }
        };

        ld(0, 0); CP_COMMIT();
        ld(1, 1); CP_COMMIT();
        // i = 0..5: steady distance-2 prefetch (loads t2..t7)
        for (int i = 0; i < 6; i++) {
            CP_WAIT1();
            __syncthreads();
            ld(i + 2, (i + 2) % 3); CP_COMMIT();
            compute_tile(smb + (uint32_t)(i % 3) * BUF_HALFS * 2, o, acc);
        }
        // i = 6: no load (tile 8 deferred behind the barrier)
        CP_WAIT1();
        __syncthreads();
        compute_tile(smb + (uint32_t)(6 % 3) * BUF_HALFS * 2, o, acc);
        // i = 7: drain, barrier spin, issue h tiles 8+9, compute 7
        CP_WAIT0();
        if (n > 0 && tid == 0) {
            const int* bp = &g_barc[(n - 1) * 16 + bmg];
            while (ld_acquire(bp) < 16) __nanosleep(64);
        }
        __syncthreads();
        ld(8, 8 % 3); CP_COMMIT();
        ld(9, 9 % 3); CP_COMMIT();
        compute_tile(smb + (uint32_t)(7 % 3) * BUF_HALFS * 2, o, acc);
        // i = 8..13: steady distance-2 (loads t10..t15)
        for (int i = 8; i < 14; i++) {
            CP_WAIT1();
            __syncthreads();
            ld(i + 2, (i + 2) % 3); CP_COMMIT();
            compute_tile(smb + (uint32_t)(i % 3) * BUF_HALFS * 2, o, acc);
        }
        // i = 14
        CP_WAIT1();
        __syncthreads();
        compute_tile(smb + (uint32_t)(14 % 3) * BUF_HALFS * 2, o, acc);
        // i = 15
        CP_WAIT0();
        __syncthreads();
        compute_tile(smb + (uint32_t)(15 % 3) * BUF_HALFS * 2, o, acc);
        __syncthreads();   // guard smem reuse by epilogue

        lstm_epilogue(acc, (float*)smh, ca.bias, ca.c, ca.c,
                      (n == NSLOT - 1) ? ca.hmem_out : nullptr,
                      (n & 1) ? ca.h0 : ca.h1,
                      ca.dt + (size_t)n * BB, ca.wdt, bm, bn, tid);

        __threadfence();       // release h/c writes
        __syncthreads();       // also guards gsm vs next step's loads
        if (tid == 0) atomicAdd(&g_barc[n * 16 + bmg], 1);
    }
}

// ------------------------- standalone GEMM kernel ----------------------------
struct GArgs {
    int lstm, K, ldw, ldc;
    Seg s;
    const __half *W;
    const float *bias, *c_in;
    float *C, *c_out, *h_full;
};

__global__ void __launch_bounds__(256, 2) mma_gemm_kernel(const GArgs a) {
    extern __shared__ __half smh[];
    const uint32_t smb = smem_u32(smh);
    const int tid = threadIdx.x;
    const int wid = tid >> 5, lane = tid & 31;
    const int wm = wid & 3, wn = wid >> 2;
    const int gid = lane >> 2, tg = lane & 3;
    const int bm = blockIdx.y * 128;
    const int bn = blockIdx.x * 128;
    const LdsmOff o = make_off(tid);
    float acc[2][8][4];

    gemm_loop(smb, a.s, a.W, a.ldw, a.K, bm, bn, tid, o, acc);

    if (a.lstm) {
        lstm_epilogue(acc, (float*)smh, a.bias, a.c_in, a.c_out, a.h_full,
                      nullptr, nullptr, nullptr, bm, bn, tid);
        return;
    }
#pragma unroll
    for (int mt = 0; mt < 2; mt++) {
        const size_t r0 = (size_t)bm + wm * 32 + mt * 16 + gid;
        const size_t r1 = r0 + 8;
#pragma unroll
        for (int nt = 0; nt < 8; nt++) {
            const int col = bn + wn * 64 + nt * 8 + tg * 2;
            float2 v0 = make_float2(acc[mt][nt][0], acc[mt][nt][1]);
            float2 v1 = make_float2(acc[mt][nt][2], acc[mt][nt][3]);
            if (a.bias) {
                float2 b2 = *(const float2*)(a.bias + col);
                v0.x += b2.x; v0.y += b2.y; v1.x += b2.x; v1.y += b2.y;
            }
            *(float2*)(a.C + r0 * a.ldc + col) = v0;
            *(float2*)(a.C + r1 * a.ldc + col) = v1;
        }
    }
}

static void launch_g(const GArgs& a, int M, int N) {
    dim3 grid(N / 128, M / 128);
    mma_gemm_kernel<<<grid, 256, SMEM_DYN>>>(a);
}

// ------------------------------ prep kernels --------------------------------
__device__ __forceinline__ int porig(int p) { return ((p & 3) << 9) | (p >> 2); }

#define Q0 ((size_t)G4 * KSTEP)
#define Q1 (Q0 + (size_t)G4 * KOUT)
#define Q2 (Q1 + (size_t)BB * DD)
#define Q3 (Q2 + (size_t)BB * HH)
#define Q4 (Q3 + (size_t)DD * DD)
#define Q5 (Q4 + G4)
#define Q6 (Q5 + G4)
#define Q7 (Q6 + G4)

__global__ void prep_kernel(const float* __restrict__ Wih, const float* __restrict__ Whh,
                            const float* __restrict__ bih, const float* __restrict__ bhh,
                            const float* __restrict__ Wiho, const float* __restrict__ Whho,
                            const float* __restrict__ biho,
                            const float* __restrict__ x, const float* __restrict__ hl,
                            const float* __restrict__ Wv) {
    size_t e = (size_t)blockIdx.x * blockDim.x + threadIdx.x;
    if (e < Q0) {
        int p = (int)(e / KSTEP), k = (int)(e % KSTEP);
        float v;
        if (k < 512) v = Whh[(size_t)porig(p) * 512 + k];
        else         v = Wih[(size_t)porig(p) * FEAT + (k - 512)];
        g_wstep[e] = __float2half_rn(v);
    } else if (e < Q1) {
        size_t i = e - Q0; int p = (int)(i / KOUT), k = (int)(i % KOUT);
        float v = (k < 768) ? Wiho[(size_t)porig(p) * 768 + k]
                            : Whho[(size_t)porig(p) * 512 + (k - 768)];
        g_wout[i] = __float2half_rn(v);
    } else if (e < Q2) {
        size_t i = e - Q1; g_xh[i] = __float2half_rn(x[i]);
    } else if (e < Q3) {
        size_t i = e - Q2; g_hlh[i] = __float2half_rn(hl[i]);
    } else if (e < Q4) {
        size_t i = e - Q3; g_wvh[i] = __float2half_rn(Wv[i]);
    } else if (e < Q5) {
        int p = (int)(e - Q4); int o = porig(p);
        g_bias[p] = bih[o] + bhh[o];
    } else if (e < Q6) {
        int p = (int)(e - Q5);
        g_biaso[p] = biho[porig(p)];
    } else if (e < Q7) {
        int p = (int)(e - Q6);
        g_wdt[p] = Wih[(size_t)porig(p) * FEAT + 512];
    }
}

__global__ void zero_hc_kernel() {
    int e = blockIdx.x * blockDim.x + threadIdx.x;
    if (e < BB * HH) { g_h0[e] = __float2half_rn(0.0f); g_c[e] = 0.0f; }
    if (e < NSLOT * 16) g_barc[e] = 0;
}

__global__ void detect_filled_kernel(const unsigned int* __restrict__ w) {
    __shared__ int flags[3];
    if (threadIdx.x < 3) flags[threadIdx.x] = 0;
    __syncthreads();
    for (int i = threadIdx.x; i < (BB * NSLOT) / 4; i += blockDim.x) {
        unsigned v = w[i];
        if (v == 0x3F800000u)      atomicOr(&flags[0], 1);
        else if (v == 0x3F803F80u) atomicOr(&flags[1], 1);
        else if (v > 1u)           atomicOr(&flags[2], 1);
    }
    __syncthreads();
    if (threadIdx.x == 0) {
        int m;
        if (flags[1])      m = 3;
        else if (flags[0]) m = 0;
        else if (flags[2]) m = 2;
        else               m = 1;
        g_fmode = m;
    }
}

// select_idx: first-empty fast path via ballot; fp32 sims only when no empty.
__global__ void select_idx_kernel(const float* __restrict__ slots,
                                  const void* __restrict__ filled,
                                  const float* __restrict__ x,
                                  const float* __restrict__ Wq,
                                  const float* __restrict__ Wk) {
    const int b = blockIdx.x;
    const int t = threadIdx.x;   // 64 threads
    __shared__ unsigned msk[2];
    int e = !read_filled(filled, (size_t)b * NSLOT + t, g_fmode);
    unsigned m = __ballot_sync(0xffffffffu, e);
    if ((t & 31) == 0) msk[t >> 5] = m;
    __syncthreads();
    if (msk[0] | msk[1]) {
        if (t == 0)
            g_idx[b] = msk[0] ? (__ffs(msk[0]) - 1) : (32 + __ffs(msk[1]) - 1);
        return;
    }
    // rare path: compute sims in fp32
    __shared__ float xs[DD], qv[HH], kq[DD], sims[NSLOT];
    for (int d = t; d < DD; d += NSLOT) xs[d] = x[b * DD + d];
    __syncthreads();
    for (int h = t; h < HH; h += NSLOT) {
        const float* wr = Wq + (size_t)h * DD;
        float s = 0.0f;
        for (int d = 0; d < DD; d++) s = fmaf(xs[d], wr[d], s);
        qv[h] = s;
    }
    __syncthreads();
    for (int d = t; d < DD; d += NSLOT) {
        float s = 0.0f;
        for (int h = 0; h < HH; h++) s = fmaf(qv[h], Wk[(size_t)h * DD + d], s);
        kq[d] = s;
    }
    __syncthreads();
    {
        const float* sp = slots + ((size_t)b * NSLOT + t) * DD;
        float s = 0.0f;
        for (int d = 0; d < DD; d++) s = fmaf(sp[d], kq[d], s);
        sims[t] = s;
    }
    __syncthreads();
    if (t == 0) {
        float best = sims[0]; int idx = 0;
        for (int n = 1; n < NSLOT; n++) if (sims[n] > best) { best = sims[n]; idx = n; }
        g_idx[b] = idx;
    }
}

__global__ void update_write_kernel(const float* __restrict__ slots,
                                    const float* __restrict__ cum,
                                    const float* __restrict__ delta,
                                    const void* __restrict__ filled,
                                    const float* __restrict__ x,
                                    float* __restrict__ out) {
    size_t e = (size_t)blockIdx.x * blockDim.x + threadIdx.x;
    if (e >= (size_t)BB * NSLOT * DD) return;
    int d = (int)(e % DD);
    size_t bn = e / DD;
    int n = (int)(bn % NSLOT);
    int b = (int)(bn / NSLOT);
    int idx = g_idx[b];

    float xv = x[b * DD + d];
    float sl = slots[e];
    float cf = cum[e] + xv;
    if (n == idx) { sl = g_v[b * DD + d]; cf = xv; }

    out[OFF_SLOTS + e] = sl;
    out[OFF_CUM + e]   = cf;

    size_t mbase = ((size_t)n * BB + b) * MEMW;
    g_mem[mbase + d]      = __float2half_rn(sl);
    g_mem[mbase + DD + d] = __float2half_rn(cf);
    if (d == 0) {
        float dt = (n == idx) ? 0.0f : delta[bn] + 1.0f;
        out[OFF_DELTA + bn] = dt;
        g_dt[(size_t)n * BB + b] = dt;
        int fl = (n == idx) ? 1 : read_filled(filled, bn, g_fmode);
        out[OFF_FILLED + bn] = fl ? 1.0f : 0.0f;
    }
}

// --------------------------------- launch -----------------------------------
extern "C" void kernel_launch(void* const* d_in, const int* in_sizes, int n_in,
                              void* d_out, int out_size) {
    const float* x_t      = (const float*)d_in[0];
    const float* h_lstm   = (const float*)d_in[1];
    const float* c_lstm   = (const float*)d_in[2];
    const float* slots    = (const float*)d_in[4];
    const float* cum      = (const float*)d_in[5];
    const float* delta    = (const float*)d_in[6];
    const void*  filled   = (const void*)d_in[7];
    const float* Wq       = (const float*)d_in[8];
    const float* Wk       = (const float*)d_in[9];
    const float* Wv       = (const float*)d_in[10];
    const float* bv       = (const float*)d_in[11];
    const float* lstm_Wih = (const float*)d_in[12];
    const float* lstm_Whh = (const float*)d_in[13];
    const float* lstm_bih = (const float*)d_in[14];
    const float* lstm_bhh = (const float*)d_in[15];
    const float* W_ih     = (const float*)d_in[16];
    const float* b_ih     = (const float*)d_in[17];
    const float* W_hh     = (const float*)d_in[18];
    float* out = (float*)d_out;

    float *p_v, *p_c, *p_bias, *p_biaso, *p_dt, *p_wdt;
    __half *p_mem, *p_wstep, *p_wout, *p_xh, *p_hlh, *p_wvh, *p_h0, *p_h1;
    cudaGetSymbolAddress((void**)&p_v, g_v);
    cudaGetSymbolAddress((void**)&p_mem, g_mem);
    cudaGetSymbolAddress((void**)&p_c, g_c);
    cudaGetSymbolAddress((void**)&p_bias, g_bias);
    cudaGetSymbolAddress((void**)&p_biaso, g_biaso);
    cudaGetSymbolAddress((void**)&p_dt, g_dt);
    cudaGetSymbolAddress((void**)&p_wdt, g_wdt);
    cudaGetSymbolAddress((void**)&p_wstep, g_wstep);
    cudaGetSymbolAddress((void**)&p_wout, g_wout);
    cudaGetSymbolAddress((void**)&p_xh, g_xh);
    cudaGetSymbolAddress((void**)&p_hlh, g_hlh);
    cudaGetSymbolAddress((void**)&p_wvh, g_wvh);
    cudaGetSymbolAddress((void**)&p_h0, g_h0);
    cudaGetSymbolAddress((void**)&p_h1, g_h1);

    static int attr_set = 0;
    if (!attr_set) {
        cudaFuncSetAttribute(mma_gemm_kernel,
                             cudaFuncAttributeMaxDynamicSharedMemorySize, SMEM_DYN);
        cudaFuncSetAttribute(chain_kernel,
                             cudaFuncAttributeMaxDynamicSharedMemorySize, SMEM_DYN);
        attr_set = 1;
    }

    detect_filled_kernel<<<1, 256>>>((const unsigned int*)filled);
    zero_hc_kernel<<<(BB * HH + 255) / 256, 256>>>();
    prep_kernel<<<(unsigned)((Q7 + 255) / 256), 256>>>(
        lstm_Wih, lstm_Whh, lstm_bih, lstm_bhh,
        W_ih, W_hh, b_ih, x_t, h_lstm, Wv);

    GArgs a;
    // v = x @ Wv.T + bv
    a = {}; a.K = 256; a.ldw = 256; a.ldc = 256;
    a.s = { p_xh, nullptr, nullptr, 256, 0, 0, 256, 256 };
    a.W = p_wvh; a.bias = bv; a.C = p_v;
    launch_g(a, BB, DD);

    select_idx_kernel<<<BB, NSLOT>>>(slots, filled, x_t, Wq, Wk);
    {
        size_t tot = (size_t)BB * NSLOT * DD;
        update_write_kernel<<<(unsigned)((tot + 255) / 256), 256>>>(
            slots, cum, delta, filled, x_t, out);
    }

    // persistent slot-LSTM chain
    {
        ChainArgs ca;
        ca.mem = p_mem; ca.W = p_wstep; ca.bias = p_bias;
        ca.dt = p_dt; ca.wdt = p_wdt;
        ca.h0 = p_h0; ca.h1 = p_h1; ca.c = p_c;
        ca.hmem_out = out + OFF_HMEM;
        chain_kernel<<<256, 256, SMEM_DYN>>>(ca);
    }

    // outer LSTM: K = [x(256) | h_mem(512) | h_lstm(512)]
    a = {}; a.lstm = 1; a.K = KOUT; a.ldw = KOUT; a.ldc = G4;
    a.s = { p_xh, p_h0, p_hlh, 256, 512, 512, 256, 768 };   // n=63 odd -> h in p_h0
    a.W = p_wout; a.bias = p_biaso;
    a.c_in = c_lstm; a.c_out = out + OFF_C; a.h_full = out + OFF_H;
    launch_g(a, BB, G4);
}